// round 8
// baseline (speedup 1.0000x reference)
#include <cuda_runtime.h>
#include <math.h>

constexpr int S = 4;
constexpr int V = 2;
constexpr int B = 8192;
constexpr int D = 512;
constexpr int KV = S * V;            // 8 vectors per batch element
constexpr float TEMP_INV = 10.0f;    // 1 / 0.1

constexpr int WARPS_PER_BLOCK = 8;
constexpr int THREADS = WARPS_PER_BLOCK * 32;
constexpr int NBLOCKS = B / WARPS_PER_BLOCK;  // 1024

// Only pairs the loss actually uses: diagonals (norms), even-odd, and
// even-even off-diagonals. Odd-odd off-diagonal dots are never read. 30 pairs.
__host__ __device__ constexpr bool pair_skip(int p, int q) {
    return (p & 1) && (q & 1) && (p != q);
}
__host__ __device__ constexpr int pidx(int p, int q) {
    int idx = 0;
    for (int a = 0; a < KV; a++)
        for (int b = a; b < KV; b++) {
            if (pair_skip(a, b)) continue;
            if (a == p && b == q) return idx;
            idx++;
        }
    return -1;
}
constexpr int NPAIR = pidx(KV - 1, KV - 1) + 1;  // 30

// Deterministic fused-reduction scratch (allocation-free)
__device__ float g_partials[NBLOCKS];
__device__ unsigned int g_done_count;  // zero-init; last block resets it

// minBlocksPerMultiprocessor=1 pins ptxas to a high-register allocation
// (~90 regs live in the mainloop). Without it the heuristic chose 40 regs
// and spilled the 30 accumulators to local memory (R3/R4: 6x regression).
__global__ void __launch_bounds__(THREADS, 1)
gram_loss_kernel(const float* __restrict__ views, float* __restrict__ out) {
    const int warp = threadIdx.x >> 5;
    const int lane = threadIdx.x & 31;
    const int b = blockIdx.x * WARPS_PER_BLOCK + warp;

    const float4* base[KV];
#pragma unroll
    for (int k = 0; k < KV; k++)
        base[k] = reinterpret_cast<const float4*>(
            views + ((size_t)k * B + b) * (size_t)D);

    float acc[NPAIR];
#pragma unroll
    for (int i = 0; i < NPAIR; i++) acc[i] = 0.0f;

    // D=512 floats = 128 float4 per vector; 32 lanes -> 4 chunks, coalesced.
#pragma unroll
    for (int c = 0; c < 4; c++) {
        float4 v[KV];
#pragma unroll
        for (int k = 0; k < KV; k++)
            v[k] = __ldg(&base[k][c * 32 + lane]);
#pragma unroll
        for (int p = 0; p < KV; p++) {
#pragma unroll
            for (int q = p; q < KV; q++) {
                if (pair_skip(p, q)) continue;
                const int id = pidx(p, q);
                float s = acc[id];
                s = fmaf(v[p].x, v[q].x, s);
                s = fmaf(v[p].y, v[q].y, s);
                s = fmaf(v[p].z, v[q].z, s);
                s = fmaf(v[p].w, v[q].w, s);
                acc[id] = s;
            }
        }
    }

    // Warp butterfly reduce the 30 partials
#pragma unroll
    for (int off = 16; off >= 1; off >>= 1) {
#pragma unroll
        for (int i = 0; i < NPAIR; i++)
            acc[i] += __shfl_xor_sync(0xffffffffu, acc[i], off);
    }

    __shared__ float warp_loss[WARPS_PER_BLOCK];
    __shared__ int sm_last;

    if (lane == 0) {
        float invn[KV];
#pragma unroll
        for (int k = 0; k < KV; k++)
            invn[k] = 1.0f / fmaxf(sqrtf(acc[pidx(k, k)]), 1e-12f);

        float loss = 0.0f;
#pragma unroll
        for (int i = 0; i < S; i++) {
            const int a = i * 2;  // anchor = (s=i, v=0)
            float l[7];
            int cnt = 0;
            l[cnt++] = acc[pidx(a, a + 1)] * invn[a] * invn[a + 1] * TEMP_INV;
#pragma unroll
            for (int j = 0; j < S; j++) {
                if (j == i) continue;
#pragma unroll
                for (int v2 = 0; v2 < V; v2++) {
                    const int jk = j * 2 + v2;
                    const int p = a < jk ? a : jk;
                    const int q = a < jk ? jk : a;
                    l[cnt++] = acc[pidx(p, q)] * invn[a] * invn[jk] * TEMP_INV;
                }
            }
            float m = l[0];
#pragma unroll
            for (int t = 1; t < 7; t++) m = fmaxf(m, l[t]);
            float se = 0.0f;
#pragma unroll
            for (int t = 0; t < 7; t++) se += __expf(l[t] - m);
            loss += m + __logf(se) - l[0];
        }
        warp_loss[warp] = loss;
    }
    __syncthreads();

    // Block partial; last finishing block does the deterministic final sum
    // (fixed per-block values + fixed summation order => deterministic).
    if (threadIdx.x == 0) {
        float s = 0.0f;
#pragma unroll
        for (int w = 0; w < WARPS_PER_BLOCK; w++) s += warp_loss[w];
        g_partials[blockIdx.x] = s;
        __threadfence();
        unsigned int t = atomicAdd(&g_done_count, 1u);
        sm_last = (t == (unsigned int)(NBLOCKS - 1)) ? 1 : 0;
    }
    __syncthreads();

    if (sm_last) {
        __threadfence();  // make all g_partials stores visible
        __shared__ float sm[THREADS];
        float s = 0.0f;
        for (int i = threadIdx.x; i < NBLOCKS; i += THREADS)
            s += g_partials[i];
        sm[threadIdx.x] = s;
        __syncthreads();
#pragma unroll
        for (int stride = THREADS / 2; stride >= 1; stride >>= 1) {
            if (threadIdx.x < stride) sm[threadIdx.x] += sm[threadIdx.x + stride];
            __syncthreads();
        }
        if (threadIdx.x == 0) {
            out[0] = sm[0] / (float)(S * B);
            g_done_count = 0;  // reset for next graph replay
        }
    }
}

extern "C" void kernel_launch(void* const* d_in, const int* in_sizes, int n_in,
                              void* d_out, int out_size) {
    const float* views = (const float*)d_in[0];
    float* out = (float*)d_out;
    gram_loss_kernel<<<NBLOCKS, THREADS>>>(views, out);
}

// round 9
// speedup vs baseline: 5.2332x; 5.2332x over previous
#include <cuda_runtime.h>
#include <math.h>

// Problem constants
constexpr int S = 4;
constexpr int V = 2;
constexpr int B = 8192;
constexpr int D = 512;
constexpr int KV = S * V;          // 8 vectors per batch element
constexpr int NPAIR = KV * (KV + 1) / 2;  // 36 upper-triangle entries
constexpr float TEMP_INV = 10.0f;  // 1 / 0.1

constexpr int WARPS_PER_BLOCK = 8;
constexpr int THREADS = WARPS_PER_BLOCK * 32;
constexpr int NBLOCKS = B / WARPS_PER_BLOCK;  // 1024

// Deterministic two-stage reduction scratch (allocation-free)
__device__ float g_partials[NBLOCKS];

__host__ __device__ constexpr int TRI(int p, int q) {
    // upper-triangle index, p <= q
    return p * KV + q - p * (p + 1) / 2;
}

__global__ void __launch_bounds__(THREADS)
gram_loss_kernel(const float* __restrict__ views) {
    const int warp = threadIdx.x >> 5;
    const int lane = threadIdx.x & 31;
    const int b = blockIdx.x * WARPS_PER_BLOCK + warp;

    // Base pointers for the 8 vectors of this batch element.
    const float4* base[KV];
#pragma unroll
    for (int k = 0; k < KV; k++)
        base[k] = reinterpret_cast<const float4*>(views + ((size_t)k * B + b) * (size_t)D);

    float acc[NPAIR];
#pragma unroll
    for (int i = 0; i < NPAIR; i++) acc[i] = 0.0f;

    // D=512 floats = 128 float4 per vector; 32 lanes -> 4 chunks.
    // Lane loads float4 index (c*32 + lane): consecutive lanes contiguous -> coalesced.
#pragma unroll
    for (int c = 0; c < 4; c++) {
        float4 v[KV];
#pragma unroll
        for (int k = 0; k < KV; k++)
            v[k] = __ldg(&base[k][c * 32 + lane]);
#pragma unroll
        for (int p = 0; p < KV; p++) {
#pragma unroll
            for (int q = p; q < KV; q++) {
                float s = acc[TRI(p, q)];
                s = fmaf(v[p].x, v[q].x, s);
                s = fmaf(v[p].y, v[q].y, s);
                s = fmaf(v[p].z, v[q].z, s);
                s = fmaf(v[p].w, v[q].w, s);
                acc[TRI(p, q)] = s;
            }
        }
    }

    // Warp butterfly reduce all 36 partials
#pragma unroll
    for (int off = 16; off >= 1; off >>= 1) {
#pragma unroll
        for (int i = 0; i < NPAIR; i++)
            acc[i] += __shfl_xor_sync(0xffffffffu, acc[i], off);
    }

    __shared__ float warp_loss[WARPS_PER_BLOCK];

    if (lane == 0) {
        // Inverse norms (clamped like the reference: maximum(norm, 1e-12))
        float invn[KV];
#pragma unroll
        for (int k = 0; k < KV; k++)
            invn[k] = 1.0f / fmaxf(sqrtf(acc[TRI(k, k)]), 1e-12f);

        float loss = 0.0f;
#pragma unroll
        for (int i = 0; i < S; i++) {
            const int a = i * 2;  // anchor = (s=i, v=0)
            float l[1 + 2 * (S - 1)];  // 7 finite logits
            int cnt = 0;
            // positive: (i,0) . (i,1)
            l[cnt++] = acc[TRI(a, a + 1)] * invn[a] * invn[a + 1] * TEMP_INV;
            // negatives: (i,0) . (j,v) for j != i  (j==i rows are -inf, dropped)
#pragma unroll
            for (int j = 0; j < S; j++) {
                if (j == i) continue;
#pragma unroll
                for (int v2 = 0; v2 < V; v2++) {
                    const int jk = j * 2 + v2;
                    const int p = a < jk ? a : jk;
                    const int q = a < jk ? jk : a;
                    l[cnt++] = acc[TRI(p, q)] * invn[a] * invn[jk] * TEMP_INV;
                }
            }
            float m = l[0];
#pragma unroll
            for (int t = 1; t < 7; t++) m = fmaxf(m, l[t]);
            float se = 0.0f;
#pragma unroll
            for (int t = 0; t < 7; t++) se += __expf(l[t] - m);
            loss += m + __logf(se) - l[0];  // logsumexp - positive logit
        }
        warp_loss[warp] = loss;
    }
    __syncthreads();

    if (threadIdx.x == 0) {
        float s = 0.0f;
#pragma unroll
        for (int w = 0; w < WARPS_PER_BLOCK; w++) s += warp_loss[w];
        g_partials[blockIdx.x] = s;
    }
}

// Slim tail: 1024 threads, one load each, warp butterfly + one smem level.
// Deterministic (fixed summation order), minimal latency.
__global__ void __launch_bounds__(1024)
final_reduce_kernel(float* __restrict__ out) {
    const int tid = threadIdx.x;
    const int warp = tid >> 5;
    const int lane = tid & 31;

    float s = g_partials[tid];  // NBLOCKS == 1024 == blockDim.x
#pragma unroll
    for (int off = 16; off >= 1; off >>= 1)
        s += __shfl_xor_sync(0xffffffffu, s, off);

    __shared__ float wsum[32];
    if (lane == 0) wsum[warp] = s;
    __syncthreads();

    if (warp == 0) {
        float t = wsum[lane];
#pragma unroll
        for (int off = 16; off >= 1; off >>= 1)
            t += __shfl_xor_sync(0xffffffffu, t, off);
        if (lane == 0) out[0] = t / (float)(S * B);
    }
}

extern "C" void kernel_launch(void* const* d_in, const int* in_sizes, int n_in,
                              void* d_out, int out_size) {
    const float* views = (const float*)d_in[0];
    float* out = (float*)d_out;
    gram_loss_kernel<<<NBLOCKS, THREADS>>>(views);
    final_reduce_kernel<<<1, 1024>>>(out);
}

// round 10
// speedup vs baseline: 5.9125x; 1.1298x over previous
#include <cuda_runtime.h>
#include <math.h>

// Problem constants
constexpr int S = 4;
constexpr int V = 2;
constexpr int B = 8192;
constexpr int D = 512;
constexpr int KV = S * V;          // 8 vectors per batch element
constexpr int NPAIR = KV * (KV + 1) / 2;  // 36 upper-triangle entries
constexpr float TEMP_INV = 10.0f;  // 1 / 0.1

// 128-thread blocks: ~90 regs/thread -> 5 blocks/SM = 20 warps/SM (vs 16 at
// 256-thread blocks), and 2048 blocks -> 2.77 waves (vs 3.46). Per-warp code
// is byte-identical to the known-good R2 compile.
constexpr int WARPS_PER_BLOCK = 4;
constexpr int THREADS = WARPS_PER_BLOCK * 32;
constexpr int NBLOCKS = B / WARPS_PER_BLOCK;  // 2048

// Deterministic two-stage reduction scratch (allocation-free)
__device__ float g_partials[NBLOCKS];

__host__ __device__ constexpr int TRI(int p, int q) {
    // upper-triangle index, p <= q
    return p * KV + q - p * (p + 1) / 2;
}

__global__ void __launch_bounds__(THREADS)
gram_loss_kernel(const float* __restrict__ views) {
    const int warp = threadIdx.x >> 5;
    const int lane = threadIdx.x & 31;
    const int b = blockIdx.x * WARPS_PER_BLOCK + warp;

    // Base pointers for the 8 vectors of this batch element.
    const float4* base[KV];
#pragma unroll
    for (int k = 0; k < KV; k++)
        base[k] = reinterpret_cast<const float4*>(views + ((size_t)k * B + b) * (size_t)D);

    float acc[NPAIR];
#pragma unroll
    for (int i = 0; i < NPAIR; i++) acc[i] = 0.0f;

    // D=512 floats = 128 float4 per vector; 32 lanes -> 4 chunks.
    // Lane loads float4 index (c*32 + lane): consecutive lanes contiguous -> coalesced.
#pragma unroll
    for (int c = 0; c < 4; c++) {
        float4 v[KV];
#pragma unroll
        for (int k = 0; k < KV; k++)
            v[k] = __ldg(&base[k][c * 32 + lane]);
#pragma unroll
        for (int p = 0; p < KV; p++) {
#pragma unroll
            for (int q = p; q < KV; q++) {
                float s = acc[TRI(p, q)];
                s = fmaf(v[p].x, v[q].x, s);
                s = fmaf(v[p].y, v[q].y, s);
                s = fmaf(v[p].z, v[q].z, s);
                s = fmaf(v[p].w, v[q].w, s);
                acc[TRI(p, q)] = s;
            }
        }
    }

    // Warp butterfly reduce all 36 partials
#pragma unroll
    for (int off = 16; off >= 1; off >>= 1) {
#pragma unroll
        for (int i = 0; i < NPAIR; i++)
            acc[i] += __shfl_xor_sync(0xffffffffu, acc[i], off);
    }

    __shared__ float warp_loss[WARPS_PER_BLOCK];

    if (lane == 0) {
        // Inverse norms (clamped like the reference: maximum(norm, 1e-12))
        float invn[KV];
#pragma unroll
        for (int k = 0; k < KV; k++)
            invn[k] = 1.0f / fmaxf(sqrtf(acc[TRI(k, k)]), 1e-12f);

        float loss = 0.0f;
#pragma unroll
        for (int i = 0; i < S; i++) {
            const int a = i * 2;  // anchor = (s=i, v=0)
            float l[1 + 2 * (S - 1)];  // 7 finite logits
            int cnt = 0;
            // positive: (i,0) . (i,1)
            l[cnt++] = acc[TRI(a, a + 1)] * invn[a] * invn[a + 1] * TEMP_INV;
            // negatives: (i,0) . (j,v) for j != i  (j==i rows are -inf, dropped)
#pragma unroll
            for (int j = 0; j < S; j++) {
                if (j == i) continue;
#pragma unroll
                for (int v2 = 0; v2 < V; v2++) {
                    const int jk = j * 2 + v2;
                    const int p = a < jk ? a : jk;
                    const int q = a < jk ? jk : a;
                    l[cnt++] = acc[TRI(p, q)] * invn[a] * invn[jk] * TEMP_INV;
                }
            }
            float m = l[0];
#pragma unroll
            for (int t = 1; t < 7; t++) m = fmaxf(m, l[t]);
            float se = 0.0f;
#pragma unroll
            for (int t = 0; t < 7; t++) se += __expf(l[t] - m);
            loss += m + __logf(se) - l[0];  // logsumexp - positive logit
        }
        warp_loss[warp] = loss;
    }
    __syncthreads();

    if (threadIdx.x == 0) {
        float s = 0.0f;
#pragma unroll
        for (int w = 0; w < WARPS_PER_BLOCK; w++) s += warp_loss[w];
        g_partials[blockIdx.x] = s;
    }
    // PDL: this block's contribution is done — allow the dependent tail
    // kernel to begin launching.
    cudaTriggerProgrammaticLaunchCompletion();
}

// Slim tail: 1024 threads. Launched with programmatic dependent launch so its
// launch latency overlaps the gram kernel's tail wave; the grid-dependency
// sync guarantees all g_partials stores are visible before we read.
__global__ void __launch_bounds__(1024)
final_reduce_kernel(float* __restrict__ out) {
    cudaGridDependencySynchronize();

    const int tid = threadIdx.x;
    const int warp = tid >> 5;
    const int lane = tid & 31;

    // NBLOCKS == 2048 == 2 * blockDim.x
    float s = g_partials[tid] + g_partials[tid + 1024];
#pragma unroll
    for (int off = 16; off >= 1; off >>= 1)
        s += __shfl_xor_sync(0xffffffffu, s, off);

    __shared__ float wsum[32];
    if (lane == 0) wsum[warp] = s;
    __syncthreads();

    if (warp == 0) {
        float t = wsum[lane];
#pragma unroll
        for (int off = 16; off >= 1; off >>= 1)
            t += __shfl_xor_sync(0xffffffffu, t, off);
        if (lane == 0) out[0] = t / (float)(S * B);
    }
}

extern "C" void kernel_launch(void* const* d_in, const int* in_sizes, int n_in,
                              void* d_out, int out_size) {
    const float* views = (const float*)d_in[0];
    float* out = (float*)d_out;

    gram_loss_kernel<<<NBLOCKS, THREADS>>>(views);

    // Tail with programmatic stream serialization (PDL): launch overlaps the
    // gram kernel; device-side cudaGridDependencySynchronize() provides the
    // ordering. Falls back to launch error -> bench fail if unsupported.
    cudaLaunchConfig_t cfg = {};
    cfg.gridDim = dim3(1, 1, 1);
    cfg.blockDim = dim3(1024, 1, 1);
    cfg.dynamicSmemBytes = 0;
    cfg.stream = 0;
    cudaLaunchAttribute attrs[1];
    attrs[0].id = cudaLaunchAttributeProgrammaticStreamSerialization;
    attrs[0].val.programmaticStreamSerializationAllowed = 1;
    cfg.attrs = attrs;
    cfg.numAttrs = 1;
    cudaLaunchKernelEx(&cfg, final_reduce_kernel, out);
}